// round 16
// baseline (speedup 1.0000x reference)
#include <cuda_runtime.h>
#include <cuda_fp16.h>
#include <math.h>
#include <stdint.h>

namespace {
constexpr int Bb = 4096, Dd = 64, Cc = 16, Hh = 512, NB = 2, NS = 8;
constexpr int SAS = 40;               // smem row stride in halves (80B)
constexpr int AT = 128 * SAS;         // A halves per buffer
constexpr int BT = 64 * SAS;          // B halves per buffer
constexpr int SMEM_SM  = (2 * AT + 2 * AT + 2 * BT) * 2 + 1024;   // prologue (2-plane A, 2 bufs)
constexpr int SMEM_BIG = (3 * (AT + BT)) * 2 + 1024;              // 1-plane A, 3 bufs
constexpr int STAGE_CTAS = 32 * 8;    // fused stage kernel grid
}

// ---------------- device scratch ----------------
__device__ __align__(16) __half g_h1h[2][Bb * Hh];
__device__ __align__(16) __half g_h2h[Bb * Hh];
__device__ __align__(16) __half g_mAh[2][Bb * Hh];
__device__ __align__(16) __half g_yinh[Bb * Dd];
__device__ __align__(16) float g_y[Bb * Dd], g_yacc[Bb * Dd];
__device__ __align__(16) float g_cb[NB * Bb * Hh], g_G3[NB * Bb * Hh], g_E1[NB * Bb * Hh];
__device__ __align__(16) float g_ld[Bb], g_psum[2][8 * Bb];
__device__ __align__(16) float g_f3p[4 * Bb * Dd];     // F3 split-K partials
__device__ int g_cnt[32];                               // F3 per-m-block arrival counters
__device__ int g_bcnt[2];                               // device-wide barrier counters
__device__ int g_bgen[2];                               // device-wide barrier generations (monotonic)
__device__ __align__(16) __half g_epsh[NB * Bb * Dd], g_epsl[NB * Bb * Dd];
__device__ __align__(16) __half g_W2f  [NB * Hh * Hh];   // [n][k] B2
__device__ __align__(16) __half g_W2Tf [NB * Hh * Hh];   // [n][k] F2
__device__ __align__(16) __half g_W3f  [NB * Hh * Dd];   // [512][64] G3
__device__ __align__(16) __half g_W3Tf [NB * Dd * Hh];   // [64][512] F3
__device__ __align__(16) __half g_W1yTf[NB * Hh * Dd];   // [512][64] F1/E1

// ---------------- helpers ----------------
__device__ __forceinline__ uint32_t sptr(const void* p) {
    return (uint32_t)__cvta_generic_to_shared(p);
}
__device__ __forceinline__ void ldm4(uint32_t a, uint32_t& r0, uint32_t& r1,
                                     uint32_t& r2, uint32_t& r3) {
    asm volatile("ldmatrix.sync.aligned.m8n8.x4.shared.b16 {%0,%1,%2,%3}, [%4];"
                 : "=r"(r0), "=r"(r1), "=r"(r2), "=r"(r3) : "r"(a));
}
__device__ __forceinline__ void mma_f16(float* c, const uint32_t* a, uint32_t b0, uint32_t b1) {
    asm volatile("mma.sync.aligned.m16n8k16.row.col.f32.f16.f16.f32 "
                 "{%0,%1,%2,%3}, {%4,%5,%6,%7}, {%8,%9}, {%0,%1,%2,%3};"
                 : "+f"(c[0]), "+f"(c[1]), "+f"(c[2]), "+f"(c[3])
                 : "r"(a[0]), "r"(a[1]), "r"(a[2]), "r"(a[3]), "r"(b0), "r"(b1));
}
__device__ __forceinline__ void cp16(void* dst, const void* src) {
    asm volatile("cp.async.cg.shared.global [%0], [%1], 16;"
                 :: "r"(sptr(dst)), "l"(src));
}
#define CP_COMMIT() asm volatile("cp.async.commit_group;" ::: "memory")
#define CP_WAIT1()  asm volatile("cp.async.wait_group 1;" ::: "memory")

__device__ __forceinline__ unsigned pack_h1(float v0, float v1) {
    return (unsigned)__half_as_ushort(__float2half_rn(v0))
         | ((unsigned)__half_as_ushort(__float2half_rn(v1)) << 16);
}
__device__ __forceinline__ float up16(unsigned w, int half) {
    return __half2float(__ushort_as_half((unsigned short)(half ? (w >> 16) : w)));
}
__device__ __forceinline__ float ftanh(float x) {
    const float cx = fminf(fmaxf(x, -15.f), 15.f);
    const float e = __expf(2.f * cx);
    return __fdividef(e - 1.f, e + 1.f);
}

// device-wide barrier: all STAGE_CTAS CTAs must be resident (guaranteed by
// launch_bounds(256,3): 444 slots >= 256). Generation counter is monotonic ->
// safe across graph replays; arrival counter self-resets.
__device__ __forceinline__ void gbar(int idx) {
    __syncthreads();
    __threadfence();
    if (threadIdx.x == 0) {
        volatile int* genp = (volatile int*)&g_bgen[idx];
        const int g = *genp;
        const int old = atomicAdd(&g_bcnt[idx], 1);
        if (old == STAGE_CTAS - 1) {
            g_bcnt[idx] = 0;
            __threadfence();
            atomicAdd(&g_bgen[idx], 1);
        } else {
            while (*genp == g) __nanosleep(40);
        }
    }
    __syncthreads();
}

struct P {
    const __half *A, *Al;           // generic A planes
    const __half *B, *B2f;          // generic B planes
    const float *G3;
    __half *mA;
    float *C, *C2;
    const float *cbias, *w1t, *bias, *b3, *E1;
    const __half *h1;
    __half *Oh;
    // fused stage pointers
    const __half *yin, *w1yt, *w2t, *w3t;
    __half *h1o, *h2o;
    float *y, *yacc, *ld, *psum, *f3p;
    const float *psumPrev;
    int stage;
    float t, cacc, cin, foldcoef;
};

// shared GEMM core: 128x64 tile, 1-plane A, BK=32, 3 bufs, 1 sync/tile
__device__ __forceinline__ void gemm_run(
    const __half* __restrict__ Ap, const __half* __restrict__ Bp,
    int lda, int ldb, int m0, int n0, int kbase, int NT,
    __half* sA, __half* sB, float (&acc)[2][4][4],
    int tid, int lane, int wm, int wn)
{
    auto issue = [&](int kt) {
        if (kt < NT) {
            const int buf = kt % 3;
            const int k0 = kbase + kt * 32;
            #pragma unroll
            for (int c = tid; c < 512; c += 256) {
                const int row = c >> 2, ku = c & 3;
                cp16(sA + buf * AT + row * SAS + ku * 8,
                     Ap + (size_t)(m0 + row) * lda + k0 + ku * 8);
            }
            {
                const int row = tid >> 2, ku = tid & 3;
                cp16(sB + buf * BT + row * SAS + ku * 8,
                     Bp + (size_t)(n0 + row) * ldb + k0 + ku * 8);
            }
        }
        CP_COMMIT();
    };

    const int l7 = lane & 7;
    const int aro = l7 + ((lane >> 3) & 1) * 8;
    const int aco = (lane >> 4) * 8;
    const int bro = l7 + (lane >> 4) * 8;
    const int bco = ((lane >> 3) & 1) * 8;

    issue(0);
    issue(1);
    for (int kt = 0; kt < NT; kt++) {
        CP_WAIT1();
        __syncthreads();
        issue(kt + 2);
        const int buf = kt % 3;
        const uint32_t bA = sptr(sA + buf * AT);
        const uint32_t bB = sptr(sB + buf * BT);
        #pragma unroll
        for (int kk = 0; kk < 2; kk++) {
            uint32_t ah[2][4], bh[2][4];
            #pragma unroll
            for (int mt = 0; mt < 2; mt++) {
                const uint32_t off = ((wm * 32 + mt * 16 + aro) * SAS + kk * 16 + aco) * 2;
                ldm4(bA + off, ah[mt][0], ah[mt][1], ah[mt][2], ah[mt][3]);
            }
            #pragma unroll
            for (int pn = 0; pn < 2; pn++) {
                const uint32_t off = ((wn * 32 + pn * 16 + bro) * SAS + kk * 16 + bco) * 2;
                ldm4(bB + off, bh[pn][0], bh[pn][1], bh[pn][2], bh[pn][3]);
            }
            #pragma unroll
            for (int mt = 0; mt < 2; mt++)
                #pragma unroll
                for (int nt = 0; nt < 4; nt++)
                    mma_f16(acc[mt][nt], ah[mt],
                            bh[nt >> 1][(nt & 1) * 2], bh[nt >> 1][(nt & 1) * 2 + 1]);
        }
    }
}

// ============ prologue kernel: 128x64 tile, 2-plane A (eps), K=64 ============
__global__ void __launch_bounds__(256, 3) pro_k(P p) {
    extern __shared__ __align__(16) char dynsmem[];
    __half* sAh = (__half*)dynsmem;
    __half* sAl = sAh + 2 * AT;
    __half* sBh = sAl + 2 * AT;

    const int tid = threadIdx.x, lane = tid & 31, wid = tid >> 5;
    const int wm = wid & 3, wn = wid >> 2;
    const int m0 = blockIdx.x * 128, by = blockIdx.y;

    const __half *Ah = p.A, *Al = p.Al, *Bfp;
    int n0;
    float* C0;
    if (by < 8) { Bfp = p.B; C0 = p.C; n0 = by * 64; }
    else        { Bfp = p.B2f; C0 = p.C2; n0 = (by - 8) * 64; }
    constexpr int NT = 2;

    auto issue = [&](int kt) {
        const int buf = kt & 1;
        const int k0 = kt * 32;
        #pragma unroll
        for (int c = tid; c < 1024; c += 256) {
            const int plane = c >> 9, cc = c & 511;
            const int row = cc >> 2, ku = cc & 3;
            cp16((plane ? sAl : sAh) + buf * AT + row * SAS + ku * 8,
                 (plane ? Al : Ah) + (size_t)(m0 + row) * 64 + k0 + ku * 8);
        }
        {
            const int row = tid >> 2, ku = tid & 3;
            cp16(sBh + buf * BT + row * SAS + ku * 8,
                 Bfp + (size_t)(n0 + row) * 64 + k0 + ku * 8);
        }
        CP_COMMIT();
    };

    const int l7 = lane & 7;
    const int aro = l7 + ((lane >> 3) & 1) * 8;
    const int aco = (lane >> 4) * 8;
    const int bro = l7 + (lane >> 4) * 8;
    const int bco = ((lane >> 3) & 1) * 8;

    float acc[2][4][4] = {};

    issue(0);
    for (int kt = 0; kt < NT; kt++) {
        if (kt + 1 < NT) { issue(kt + 1); CP_WAIT1(); }
        else { asm volatile("cp.async.wait_group 0;" ::: "memory"); }
        __syncthreads();
        const int buf = kt & 1;
        const uint32_t bAh = sptr(sAh + buf * AT);
        const uint32_t bAl = sptr(sAl + buf * AT);
        const uint32_t bBh = sptr(sBh + buf * BT);
        #pragma unroll
        for (int kk = 0; kk < 2; kk++) {
            uint32_t ah[2][4], al[2][4], bh[2][4];
            #pragma unroll
            for (int mt = 0; mt < 2; mt++) {
                const uint32_t off = ((wm * 32 + mt * 16 + aro) * SAS + kk * 16 + aco) * 2;
                ldm4(bAh + off, ah[mt][0], ah[mt][1], ah[mt][2], ah[mt][3]);
                ldm4(bAl + off, al[mt][0], al[mt][1], al[mt][2], al[mt][3]);
            }
            #pragma unroll
            for (int pn = 0; pn < 2; pn++) {
                const uint32_t off = ((wn * 32 + pn * 16 + bro) * SAS + kk * 16 + bco) * 2;
                ldm4(bBh + off, bh[pn][0], bh[pn][1], bh[pn][2], bh[pn][3]);
            }
            #pragma unroll
            for (int mt = 0; mt < 2; mt++)
                #pragma unroll
                for (int nt = 0; nt < 4; nt++) {
                    const uint32_t b0 = bh[nt >> 1][(nt & 1) * 2], b1 = bh[nt >> 1][(nt & 1) * 2 + 1];
                    mma_f16(acc[mt][nt], ah[mt], b0, b1);
                    mma_f16(acc[mt][nt], al[mt], b0, b1);
                }
        }
        __syncthreads();
    }

    const int g = lane >> 2, tt = lane & 3;
    #pragma unroll
    for (int mt = 0; mt < 2; mt++)
        #pragma unroll
        for (int nt = 0; nt < 4; nt++) {
            const int c = n0 + wn * 32 + nt * 8 + tt * 2;
            #pragma unroll
            for (int hr = 0; hr < 2; hr++) {
                const int r = m0 + wm * 32 + mt * 16 + g + hr * 8;
                *(float2*)&C0[(size_t)r * 512 + c] =
                    make_float2(acc[mt][nt][hr * 2 + 0], acc[mt][nt][hr * 2 + 1]);
            }
        }
}

// ============ FUSED stage kernel: F1 -> gbar -> F2 -> gbar -> F3(split-K)+RK4 ============
// grid (32,8), 256 threads, all CTAs co-resident
__global__ void __launch_bounds__(256, 3) stage_k(P p) {
    extern __shared__ __align__(16) char dynsmem[];
    __half* sA = (__half*)dynsmem;
    __half* sB = sA + 3 * AT;

    const int tid = threadIdx.x, lane = tid & 31, wid = tid >> 5;
    const int wm = wid & 3, wn = wid >> 2;
    const int m0 = blockIdx.x * 128, by = blockIdx.y;
    const int n0 = by * 64;
    const int g = lane >> 2, tt = lane & 3;

    // ---- Phase 1: F1 (K=64) -> h1 ----
    {
        float acc[2][4][4] = {};
        gemm_run(p.yin, p.w1yt, 64, 64, m0, n0, 0, 2, sA, sB, acc, tid, lane, wm, wn);
        #pragma unroll
        for (int mt = 0; mt < 2; mt++)
            #pragma unroll
            for (int nt = 0; nt < 4; nt++) {
                const int c = n0 + wn * 32 + nt * 8 + tt * 2;
                const float2 wt = *(const float2*)&p.w1t[c];
                #pragma unroll
                for (int hr = 0; hr < 2; hr++) {
                    const int r = m0 + wm * 32 + mt * 16 + g + hr * 8;
                    const size_t off = (size_t)r * 512 + c;
                    const float2 cb = *(const float2*)&p.cbias[off];
                    const float v0 = ftanh(acc[mt][nt][hr * 2 + 0] + cb.x + p.t * wt.x);
                    const float v1 = ftanh(acc[mt][nt][hr * 2 + 1] + cb.y + p.t * wt.y);
                    ((unsigned*)p.h1o)[off >> 1] = pack_h1(v0, v1);
                }
            }
    }
    gbar(0);

    // ---- Phase 2: F2 (K=512) -> h2 + mA ----
    {
        float acc[2][4][4] = {};
        gemm_run(p.h1o, p.w2t, 512, 512, m0, n0, 0, 16, sA, sB, acc, tid, lane, wm, wn);
        #pragma unroll
        for (int mt = 0; mt < 2; mt++)
            #pragma unroll
            for (int nt = 0; nt < 4; nt++) {
                const int c = n0 + wn * 32 + nt * 8 + tt * 2;
                const float2 bi = *(const float2*)&p.bias[c];
                #pragma unroll
                for (int hr = 0; hr < 2; hr++) {
                    const int r = m0 + wm * 32 + mt * 16 + g + hr * 8;
                    const size_t off = (size_t)r * 512 + c;
                    const float v0 = ftanh(acc[mt][nt][hr * 2 + 0] + bi.x);
                    const float v1 = ftanh(acc[mt][nt][hr * 2 + 1] + bi.y);
                    ((unsigned*)p.h2o)[off >> 1] = pack_h1(v0, v1);
                    const float2 gv = *(const float2*)&p.G3[off];
                    ((unsigned*)p.mA)[off >> 1] =
                        pack_h1(gv.x * (1.f - v0 * v0), gv.y * (1.f - v1 * v1));
                }
            }
    }
    gbar(1);

    // ---- Phase 3: F3 split-K (by<4) + RK4 ----
    if (by >= 4) return;
    {
        float acc[2][4][4] = {};
        gemm_run(p.h2o, p.w3t, 512, 512, m0, 0, by * 128, 4, sA, sB, acc, tid, lane, wm, wn);
        float* part = p.f3p + (size_t)by * Bb * Dd;
        #pragma unroll
        for (int mt = 0; mt < 2; mt++)
            #pragma unroll
            for (int nt = 0; nt < 4; nt++) {
                const int c = wn * 32 + nt * 8 + tt * 2;
                #pragma unroll
                for (int hr = 0; hr < 2; hr++) {
                    const int r = m0 + wm * 32 + mt * 16 + g + hr * 8;
                    *(float2*)&part[(size_t)r * 64 + c] =
                        make_float2(acc[mt][nt][hr * 2 + 0], acc[mt][nt][hr * 2 + 1]);
                }
            }
        __threadfence();
        __shared__ int isLast;
        if (tid == 0) {
            const int old = atomicAdd(&g_cnt[blockIdx.x], 1);
            isLast = (old == 3);
            if (old == 3) g_cnt[blockIdx.x] = 0;
        }
        __syncthreads();
        if (!isLast) return;

        for (int i = tid; i < 128 * 16; i += 256) {
            const int row = i >> 4, c4 = (i & 15) * 4;
            const size_t idx = (size_t)(m0 + row) * 64 + c4;
            const float4 v0 = *(const float4*)&p.f3p[idx];
            const float4 v1 = *(const float4*)&p.f3p[(size_t)Bb * Dd + idx];
            const float4 v2 = *(const float4*)&p.f3p[2 * (size_t)Bb * Dd + idx];
            const float4 v3 = *(const float4*)&p.f3p[3 * (size_t)Bb * Dd + idx];
            const float4 b3v = *(const float4*)&p.b3[c4];
            float kv[4] = {(v0.x + v1.x) + (v2.x + v3.x) + b3v.x,
                           (v0.y + v1.y) + (v2.y + v3.y) + b3v.y,
                           (v0.z + v1.z) + (v2.z + v3.z) + b3v.z,
                           (v0.w + v1.w) + (v2.w + v3.w) + b3v.w};
            const float4 base = (p.stage == 1) ? *(const float4*)&p.y[idx]
                                               : *(const float4*)&p.yacc[idx];
            float ya[4] = {base.x + p.cacc * kv[0], base.y + p.cacc * kv[1],
                           base.z + p.cacc * kv[2], base.w + p.cacc * kv[3]};
            float yi[4];
            if (p.stage == 4) {
                *(float4*)&p.y[idx] = make_float4(ya[0], ya[1], ya[2], ya[3]);
                yi[0] = ya[0]; yi[1] = ya[1]; yi[2] = ya[2]; yi[3] = ya[3];
            } else {
                *(float4*)&p.yacc[idx] = make_float4(ya[0], ya[1], ya[2], ya[3]);
                const float4 yv = *(const float4*)&p.y[idx];
                yi[0] = yv.x + p.cin * kv[0]; yi[1] = yv.y + p.cin * kv[1];
                yi[2] = yv.z + p.cin * kv[2]; yi[3] = yv.w + p.cin * kv[3];
            }
            uint2 hh;
            hh.x = pack_h1(yi[0], yi[1]);
            hh.y = pack_h1(yi[2], yi[3]);
            *(uint2*)&((unsigned*)p.Oh)[idx >> 1] = hh;
        }
    }
}

// ============ B2 kernel (stream 2): by<8 B2 + logdet; by==8 fold rider ============
__global__ void __launch_bounds__(256, 3) b2_k(P p) {
    extern __shared__ __align__(16) char dynsmem[];
    __half* sA = (__half*)dynsmem;
    __half* sB = sA + 3 * AT;
    float* red = (float*)(sB + 3 * BT);

    const int tid = threadIdx.x, lane = tid & 31, wid = tid >> 5;
    const int wm = wid & 3, wn = wid >> 2;
    const int m0 = blockIdx.x * 128, by = blockIdx.y;

    if (by == 8) {
        if (p.foldcoef != 0.f && tid < 128) {
            const int m = m0 + tid;
            float s = 0.f;
            #pragma unroll
            for (int c = 0; c < 8; c++) s += p.psumPrev[c * Bb + m];
            p.ld[m] += p.foldcoef * s;
        }
        return;
    }

    const int n0 = by * 64;
    float acc[2][4][4] = {};
    gemm_run(p.A, p.B, 512, 512, m0, n0, 0, 16, sA, sB, acc, tid, lane, wm, wn);

    const int g = lane >> 2, tt = lane & 3;
    float s[4] = {0.f, 0.f, 0.f, 0.f};
    #pragma unroll
    for (int mt = 0; mt < 2; mt++)
        #pragma unroll
        for (int nt = 0; nt < 4; nt++) {
            const int c = n0 + wn * 32 + nt * 8 + tt * 2;
            #pragma unroll
            for (int hr = 0; hr < 2; hr++) {
                const int r = m0 + wm * 32 + mt * 16 + g + hr * 8;
                const size_t off = (size_t)r * 512 + c;
                const unsigned hh = *(const unsigned*)&p.h1[off];
                const float2 e = *(const float2*)&p.E1[off];
                const float h0 = up16(hh, 0), h1v = up16(hh, 1);
                s[mt * 2 + hr] += acc[mt][nt][hr * 2 + 0] * (1.f - h0 * h0) * e.x
                                + acc[mt][nt][hr * 2 + 1] * (1.f - h1v * h1v) * e.y;
            }
        }
    #pragma unroll
    for (int i = 0; i < 4; i++) {
        s[i] += __shfl_xor_sync(0xffffffffu, s[i], 1);
        s[i] += __shfl_xor_sync(0xffffffffu, s[i], 2);
    }
    __syncthreads();
    if (tt == 0) {
        #pragma unroll
        for (int mt = 0; mt < 2; mt++)
            #pragma unroll
            for (int hr = 0; hr < 2; hr++)
                red[(wm * 32 + mt * 16 + g + hr * 8) * 2 + wn] = s[mt * 2 + hr];
    }
    __syncthreads();
    if (tid < 128)
        p.psum[(size_t)by * Bb + m0 + tid] = red[tid * 2] + red[tid * 2 + 1];
}

// ---------------- aux kernels ----------------
__device__ __forceinline__ void hsplit(float v, __half* h, __half* l, size_t i) {
    const __half hv = __float2half_rn(v);
    h[i] = hv;
    l[i] = __float2half_rn(v - __half2float(hv));
}
__global__ void prep_k(const float* __restrict__ eps, const float* __restrict__ W2,
                       const float* __restrict__ W3, const float* __restrict__ W1,
                       __half* eph, __half* epl,
                       __half* w2f, __half* w3f,
                       __half* w2tf, __half* w1ytf, __half* w3tf) {
    int i = blockIdx.x * 256 + threadIdx.x;
    if (i < Bb * Dd) { hsplit(eps[i], eph, epl, i); return; }
    i -= Bb * Dd;
    if (i < Hh * Hh) { w2f[i] = __float2half_rn(W2[i]); return; }
    i -= Hh * Hh;
    if (i < Hh * Dd) { w3f[i] = __float2half_rn(W3[i]); return; }
    i -= Hh * Dd;
    if (i < Hh * Hh) {
        const int r = i / Hh, c = i % Hh;
        w2tf[(size_t)c * Hh + r] = __float2half_rn(W2[i]);
        return;
    }
    i -= Hh * Hh;
    if (i < Dd * Hh) {
        const int r = i / Hh, c = i % Hh;
        w1ytf[(size_t)c * Dd + r] = __float2half_rn(W1[i]);
        return;
    }
    i -= Dd * Hh;
    if (i < Hh * Dd) {
        const int r = i / Dd, c = i % Dd;
        w3tf[(size_t)c * Hh + r] = __float2half_rn(W3[i]);
    }
}
__global__ void cbias_k(const float* __restrict__ cond, const float* __restrict__ W1c,
                        const float* __restrict__ b1, float* __restrict__ cb) {
    const int m = blockIdx.x;
    const int n = threadIdx.x * 4;
    float4 acc = *(const float4*)(b1 + n);
    #pragma unroll
    for (int k = 0; k < Cc; k++) {
        const float c = cond[m * Cc + k];
        const float4 w = *(const float4*)(W1c + (size_t)k * Hh + n);
        acc.x = fmaf(c, w.x, acc.x); acc.y = fmaf(c, w.y, acc.y);
        acc.z = fmaf(c, w.z, acc.z); acc.w = fmaf(c, w.w, acc.w);
    }
    *(float4*)(cb + (size_t)m * Hh + n) = acc;
}
__global__ void init_k(const float* __restrict__ x, float* __restrict__ y,
                       __half* __restrict__ yinh, float* __restrict__ ld,
                       int* __restrict__ cnt) {
    const int i = blockIdx.x * blockDim.x + threadIdx.x;
    if (i < Bb * Dd) {
        const float v = x[i];
        y[i] = v;
        yinh[i] = __float2half_rn(v);
    }
    if (i < Bb) ld[i] = 0.f;
    if (i < 32) cnt[i] = 0;
}
__global__ void out_k(const float* __restrict__ y, const float* __restrict__ ld,
                      const float* __restrict__ psum, float coef, float* __restrict__ out) {
    const int i = blockIdx.x * blockDim.x + threadIdx.x;
    if (i >= Bb * (Dd + 1)) return;
    const int m = i / (Dd + 1), c = i % (Dd + 1);
    if (c < Dd) {
        out[i] = y[(size_t)m * Dd + c];
    } else {
        float s = 0.f;
        #pragma unroll
        for (int c2 = 0; c2 < 8; c2++) s += psum[c2 * Bb + m];
        out[i] = ld[m] + coef * s;
    }
}

// ---------------- host ----------------
extern "C" void kernel_launch(void* const* d_in, const int* in_sizes, int n_in,
                              void* d_out, int out_size) {
    const float* x    = (const float*)d_in[0];
    const float* cond = (const float*)d_in[1];
    const float* eps  = (const float*)d_in[2];
    const float* W1   = (const float*)d_in[3];
    const float* b1   = (const float*)d_in[4];
    const float* W2   = (const float*)d_in[5];
    const float* b2   = (const float*)d_in[6];
    const float* W3   = (const float*)d_in[7];
    const float* b3   = (const float*)d_in[8];
    float* out = (float*)d_out;

    static cudaStream_t s2 = nullptr;
    static cudaEvent_t evS = nullptr, evB2a = nullptr, evB2b = nullptr;
    if (s2 == nullptr) {
        cudaStreamCreateWithFlags(&s2, cudaStreamNonBlocking);
        cudaEventCreateWithFlags(&evS, cudaEventDisableTiming);
        cudaEventCreateWithFlags(&evB2a, cudaEventDisableTiming);
        cudaEventCreateWithFlags(&evB2b, cudaEventDisableTiming);
        cudaFuncSetAttribute(pro_k, cudaFuncAttributeMaxDynamicSharedMemorySize, SMEM_SM);
        cudaFuncSetAttribute(stage_k, cudaFuncAttributeMaxDynamicSharedMemorySize, SMEM_BIG);
        cudaFuncSetAttribute(b2_k, cudaFuncAttributeMaxDynamicSharedMemorySize, SMEM_BIG);
    }

    #define SYM(T, v, s) T* v; { void* _p; cudaGetSymbolAddress(&_p, s); v = (T*)_p; }
    SYM(float, y, g_y) SYM(float, yacc, g_yacc) SYM(float, cb, g_cb)
    SYM(float, G3, g_G3) SYM(float, E1, g_E1) SYM(float, ld, g_ld) SYM(float, psum, g_psum)
    SYM(float, f3p, g_f3p) SYM(int, cnt, g_cnt)
    SYM(__half, h1h, g_h1h) SYM(__half, h2h, g_h2h) SYM(__half, mAh, g_mAh)
    SYM(__half, yinh, g_yinh)
    SYM(__half, epsh, g_epsh) SYM(__half, epsl, g_epsl)
    SYM(__half, W2f, g_W2f) SYM(__half, W2Tf, g_W2Tf)
    SYM(__half, W3f, g_W3f) SYM(__half, W3Tf, g_W3Tf)
    SYM(__half, W1yTf, g_W1yTf)
    #undef SYM

    init_k<<<(Bb * Dd + 255) / 256, 256>>>(x, y, yinh, ld, cnt);

    constexpr int PREP_N = Bb * Dd + 2 * Hh * Hh + 3 * Hh * Dd;
    const float dt = 1.0f / NS;
    float prev_cl = 0.f;
    int gs = 0;

    for (int ib = 0; ib < NB; ib++) {
        const float* W1b  = W1 + (size_t)ib * (Dd + Cc + 1) * Hh;
        const float* b1b  = b1 + (size_t)ib * Hh;
        const float* W2b  = W2 + (size_t)ib * Hh * Hh;
        const float* b2b  = b2 + (size_t)ib * Hh;
        const float* W3b  = W3 + (size_t)ib * Hh * Dd;
        const float* b3b  = b3 + (size_t)ib * Dd;
        const float* epsb = eps + (size_t)ib * Bb * Dd;
        float* cbb = cb + (size_t)ib * Bb * Hh;
        float* G3b = G3 + (size_t)ib * Bb * Hh;
        float* E1b = E1 + (size_t)ib * Bb * Hh;
        __half *eph = epsh + (size_t)ib * Bb * Dd, *epl = epsl + (size_t)ib * Bb * Dd;
        __half* w2f  = W2f  + (size_t)ib * Hh * Hh;
        __half* w2tf = W2Tf + (size_t)ib * Hh * Hh;
        __half* w3f  = W3f  + (size_t)ib * Hh * Dd;
        __half* w3tf = W3Tf + (size_t)ib * Dd * Hh;
        __half* w1ytf = W1yTf + (size_t)ib * Hh * Dd;

        prep_k<<<(PREP_N + 255) / 256, 256>>>(epsb, W2b, W3b, W1b,
            eph, epl, w2f, w3f, w2tf, w1ytf, w3tf);
        cbias_k<<<Bb, 128>>>(cond, W1b + (size_t)Dd * Hh, b1b, cbb);

        {   // merged G3 (by<8) + E1 (by>=8)
            P p{}; p.A = eph; p.Al = epl;
            p.B = w3f; p.C = G3b;
            p.B2f = w1ytf; p.C2 = E1b;
            pro_k<<<dim3(32, 16), 256, SMEM_SM>>>(p);
        }

        for (int is = 0; is < NS; is++) {
            const float tbase = is * dt;
            for (int st = 1; st <= 4; st++) {
                const float t = tbase + (st == 1 ? 0.f : (st == 4 ? dt : 0.5f * dt));
                const float cacc = (st == 1 || st == 4) ? dt / 6.f : dt / 3.f;
                const float cin  = (st == 3) ? dt : 0.5f * dt;
                const int q = gs & 1;
                __half* h1q = h1h + (size_t)q * Bb * Hh;
                __half* mAq = mAh + (size_t)q * Bb * Hh;
                float* psq  = psum + (size_t)q * 8 * Bb;
                float* pspv = psum + (size_t)(q ^ 1) * 8 * Bb;
                cudaEvent_t evq = q ? evB2b : evB2a;

                if (gs >= 2) cudaStreamWaitEvent(0, evq, 0);   // h1[q]/mA[q] free

                {   // FUSED stage: F1 -> F2 -> F3 (one launch)
                    P p{};
                    p.yin = yinh; p.w1yt = w1ytf;
                    p.cbias = cbb; p.w1t = W1b + (size_t)(Dd + Cc) * Hh; p.t = t;
                    p.h1o = h1q;
                    p.w2t = w2tf; p.bias = b2b; p.h2o = h2h; p.G3 = G3b; p.mA = mAq;
                    p.w3t = w3tf; p.f3p = f3p; p.b3 = b3b;
                    p.y = y; p.yacc = yacc; p.Oh = yinh;
                    p.stage = st; p.cacc = cacc; p.cin = cin;
                    stage_k<<<dim3(32, 8), 256, SMEM_BIG>>>(p);
                }
                cudaEventRecord(evS, 0);
                cudaStreamWaitEvent(s2, evS, 0);
                {   // B2 + logdet -> psum[q]; fold rider for psum[q^1] (stream 2)
                    P p{}; p.A = mAq; p.B = w2f;
                    p.h1 = h1q; p.E1 = E1b;
                    p.psum = psq; p.psumPrev = pspv;
                    p.ld = ld; p.foldcoef = prev_cl;
                    b2_k<<<dim3(32, 9), 256, SMEM_BIG, s2>>>(p);
                }
                cudaEventRecord(evq, s2);

                prev_cl = cacc;
                gs++;
            }
        }
    }

    cudaStreamWaitEvent(0, evB2a, 0);
    cudaStreamWaitEvent(0, evB2b, 0);
    out_k<<<(Bb * (Dd + 1) + 255) / 256, 256>>>(
        y, ld, psum + (size_t)((gs - 1) & 1) * 8 * Bb, prev_cl, out);
}

// round 17
// speedup vs baseline: 1.3894x; 1.3894x over previous
#include <cuda_runtime.h>
#include <cuda_fp16.h>
#include <math.h>
#include <stdint.h>

namespace {
constexpr int Bb = 4096, Dd = 64, Cc = 16, Hh = 512, NB = 2, NS = 8;
constexpr int SAS = 40;               // smem row stride in halves (80B)
constexpr int AT = 128 * SAS;         // A halves per buffer
constexpr int BT = 64 * SAS;          // B halves per buffer
constexpr int SMEM_SM  = (2 * AT + 2 * AT + 2 * BT) * 2 + 1024;   // prologue (2-plane A, 2 bufs)
constexpr int SMEM_BIG = (4 * (AT + BT)) * 2 + 1024;              // 1-plane A, 4 bufs
}

// ---------------- device scratch ----------------
__device__ __align__(16) __half g_h1h[2][Bb * Hh];
__device__ __align__(16) __half g_h2h[Bb * Hh];
__device__ __align__(16) __half g_mAh[2][Bb * Hh];
__device__ __align__(16) __half g_yinh[Bb * Dd];
__device__ __align__(16) float g_y[Bb * Dd], g_yacc[Bb * Dd];
__device__ __align__(16) float g_cb[NB * Bb * Hh], g_G3[NB * Bb * Hh], g_E1[NB * Bb * Hh];
__device__ __align__(16) float g_ld[Bb], g_psum[2][8 * Bb];
__device__ __align__(16) __half g_epsh[NB * Bb * Dd], g_epsl[NB * Bb * Dd];
__device__ __align__(16) __half g_W2f  [NB * Hh * Hh];   // [n][k] B2
__device__ __align__(16) __half g_W2Tf [NB * Hh * Hh];   // [n][k] F2
__device__ __align__(16) __half g_W3f  [NB * Hh * Dd];   // [512][64] G3
__device__ __align__(16) __half g_W3Tf [NB * Dd * Hh];   // [64][512] F3
__device__ __align__(16) __half g_W1yTf[NB * Hh * Dd];   // [512][64] F1/E1

// ---------------- helpers ----------------
__device__ __forceinline__ uint32_t sptr(const void* p) {
    return (uint32_t)__cvta_generic_to_shared(p);
}
__device__ __forceinline__ void ldm4(uint32_t a, uint32_t& r0, uint32_t& r1,
                                     uint32_t& r2, uint32_t& r3) {
    asm volatile("ldmatrix.sync.aligned.m8n8.x4.shared.b16 {%0,%1,%2,%3}, [%4];"
                 : "=r"(r0), "=r"(r1), "=r"(r2), "=r"(r3) : "r"(a));
}
__device__ __forceinline__ void mma_f16(float* c, const uint32_t* a, uint32_t b0, uint32_t b1) {
    asm volatile("mma.sync.aligned.m16n8k16.row.col.f32.f16.f16.f32 "
                 "{%0,%1,%2,%3}, {%4,%5,%6,%7}, {%8,%9}, {%0,%1,%2,%3};"
                 : "+f"(c[0]), "+f"(c[1]), "+f"(c[2]), "+f"(c[3])
                 : "r"(a[0]), "r"(a[1]), "r"(a[2]), "r"(a[3]), "r"(b0), "r"(b1));
}
__device__ __forceinline__ void cp16(void* dst, const void* src) {
    asm volatile("cp.async.cg.shared.global [%0], [%1], 16;"
                 :: "r"(sptr(dst)), "l"(src));
}
#define CP_COMMIT() asm volatile("cp.async.commit_group;" ::: "memory")
#define CP_WAIT1()  asm volatile("cp.async.wait_group 1;" ::: "memory")
#define CP_WAIT2()  asm volatile("cp.async.wait_group 2;" ::: "memory")

__device__ __forceinline__ unsigned pack_h1(float v0, float v1) {
    return (unsigned)__half_as_ushort(__float2half_rn(v0))
         | ((unsigned)__half_as_ushort(__float2half_rn(v1)) << 16);
}
__device__ __forceinline__ float up16(unsigned w, int half) {
    return __half2float(__ushort_as_half((unsigned short)(half ? (w >> 16) : w)));
}
__device__ __forceinline__ float ftanh(float x) {
    const float cx = fminf(fmaxf(x, -15.f), 15.f);
    const float e = __expf(2.f * cx);
    return __fdividef(e - 1.f, e + 1.f);
}

struct P {
    const __half *A, *Al;
    const __half *B, *B2f;
    const float *G3;
    __half *mA;
    float *C, *C2;
    const float *cbias, *w1t, *bias, *b3, *E1;
    const __half *h1;
    __half *Oh;
    float *y, *yacc, *ld, *psum;
    const float *psumPrev;
    int stage;
    float t, cacc, cin, foldcoef;
};

// ============ prologue kernel: 128x64 tile, 2-plane A (eps), K=64, 2 bufs ============
__global__ void __launch_bounds__(256, 3) pro_k(P p) {
    extern __shared__ __align__(16) char dynsmem[];
    __half* sAh = (__half*)dynsmem;
    __half* sAl = sAh + 2 * AT;
    __half* sBh = sAl + 2 * AT;

    const int tid = threadIdx.x, lane = tid & 31, wid = tid >> 5;
    const int wm = wid & 3, wn = wid >> 2;
    const int m0 = blockIdx.x * 128, by = blockIdx.y;

    const __half *Ah = p.A, *Al = p.Al, *Bfp;
    int n0;
    float* C0;
    if (by < 8) { Bfp = p.B; C0 = p.C; n0 = by * 64; }
    else        { Bfp = p.B2f; C0 = p.C2; n0 = (by - 8) * 64; }
    constexpr int NT = 2;

    auto issue = [&](int kt) {
        const int buf = kt & 1;
        const int k0 = kt * 32;
        #pragma unroll
        for (int c = tid; c < 1024; c += 256) {
            const int plane = c >> 9, cc = c & 511;
            const int row = cc >> 2, ku = cc & 3;
            cp16((plane ? sAl : sAh) + buf * AT + row * SAS + ku * 8,
                 (plane ? Al : Ah) + (size_t)(m0 + row) * 64 + k0 + ku * 8);
        }
        {
            const int row = tid >> 2, ku = tid & 3;
            cp16(sBh + buf * BT + row * SAS + ku * 8,
                 Bfp + (size_t)(n0 + row) * 64 + k0 + ku * 8);
        }
        CP_COMMIT();
    };

    const int l7 = lane & 7;
    const int aro = l7 + ((lane >> 3) & 1) * 8;
    const int aco = (lane >> 4) * 8;
    const int bro = l7 + (lane >> 4) * 8;
    const int bco = ((lane >> 3) & 1) * 8;

    float acc[2][4][4] = {};

    issue(0);
    for (int kt = 0; kt < NT; kt++) {
        if (kt + 1 < NT) { issue(kt + 1); CP_WAIT1(); }
        else { asm volatile("cp.async.wait_group 0;" ::: "memory"); }
        __syncthreads();
        const int buf = kt & 1;
        const uint32_t bAh = sptr(sAh + buf * AT);
        const uint32_t bAl = sptr(sAl + buf * AT);
        const uint32_t bBh = sptr(sBh + buf * BT);
        #pragma unroll
        for (int kk = 0; kk < 2; kk++) {
            uint32_t ah[2][4], al[2][4], bh[2][4];
            #pragma unroll
            for (int mt = 0; mt < 2; mt++) {
                const uint32_t off = ((wm * 32 + mt * 16 + aro) * SAS + kk * 16 + aco) * 2;
                ldm4(bAh + off, ah[mt][0], ah[mt][1], ah[mt][2], ah[mt][3]);
                ldm4(bAl + off, al[mt][0], al[mt][1], al[mt][2], al[mt][3]);
            }
            #pragma unroll
            for (int pn = 0; pn < 2; pn++) {
                const uint32_t off = ((wn * 32 + pn * 16 + bro) * SAS + kk * 16 + bco) * 2;
                ldm4(bBh + off, bh[pn][0], bh[pn][1], bh[pn][2], bh[pn][3]);
            }
            #pragma unroll
            for (int mt = 0; mt < 2; mt++)
                #pragma unroll
                for (int nt = 0; nt < 4; nt++) {
                    const uint32_t b0 = bh[nt >> 1][(nt & 1) * 2], b1 = bh[nt >> 1][(nt & 1) * 2 + 1];
                    mma_f16(acc[mt][nt], ah[mt], b0, b1);
                    mma_f16(acc[mt][nt], al[mt], b0, b1);
                }
        }
        __syncthreads();
    }

    const int g = lane >> 2, tt = lane & 3;
    #pragma unroll
    for (int mt = 0; mt < 2; mt++)
        #pragma unroll
        for (int nt = 0; nt < 4; nt++) {
            const int c = n0 + wn * 32 + nt * 8 + tt * 2;
            #pragma unroll
            for (int hr = 0; hr < 2; hr++) {
                const int r = m0 + wm * 32 + mt * 16 + g + hr * 8;
                *(float2*)&C0[(size_t)r * 512 + c] =
                    make_float2(acc[mt][nt][hr * 2 + 0], acc[mt][nt][hr * 2 + 1]);
            }
        }
}

// ============ big kernel: 128x64 tile, 1-plane A, BK=32, 4 bufs, depth-2 prefetch ============
// MODE 1: F1 (K=64, tanh+cbias+t*w1t -> h1[q])      grid (32,8)
// MODE 2: F2 (K=512, tanh -> h2 + mA[q])            grid (32,8)
// MODE 3: by<8 B2 (K=512, logdet->psum[q]); by==8 fold psumPrev   grid (32,9)
// MODE 4: F3 (K=512, A=h2, RK4 -> y/yacc/yin)       grid (32,1)
template <int MODE>
__global__ void __launch_bounds__(256, 3) big_k(P p) {
    extern __shared__ __align__(16) char dynsmem[];
    __half* sA = (__half*)dynsmem;          // 4 * AT
    __half* sB = sA + 4 * AT;               // 4 * BT
    float* red = (float*)(sB + 4 * BT);

    const int tid = threadIdx.x, lane = tid & 31, wid = tid >> 5;
    const int wm = wid & 3, wn = wid >> 2;
    const int m0 = blockIdx.x * 128, by = blockIdx.y;

    if (MODE == 3 && by == 8) {   // fold rider
        if (p.foldcoef != 0.f && tid < 128) {
            const int m = m0 + tid;
            float s = 0.f;
            #pragma unroll
            for (int c = 0; c < 8; c++) s += p.psumPrev[c * Bb + m];
            p.ld[m] += p.foldcoef * s;
        }
        return;
    }

    const int lda = (MODE == 1) ? 64 : 512;
    const int ldb = lda;
    const int n0  = (MODE == 4) ? 0 : by * 64;
    const int NT = (MODE == 1) ? 2 : 16;
    const __half* Ap = p.A;
    const __half* Bp = p.B;

    auto issue = [&](int kt) {
        if (kt < NT) {
            const int buf = kt & 3;
            const int k0 = kt * 32;
            #pragma unroll
            for (int c = tid; c < 512; c += 256) {
                const int row = c >> 2, ku = c & 3;
                cp16(sA + buf * AT + row * SAS + ku * 8,
                     Ap + (size_t)(m0 + row) * lda + k0 + ku * 8);
            }
            {
                const int row = tid >> 2, ku = tid & 3;
                cp16(sB + buf * BT + row * SAS + ku * 8,
                     Bp + (size_t)(n0 + row) * ldb + k0 + ku * 8);
            }
        }
        CP_COMMIT();
    };

    const int l7 = lane & 7;
    const int aro = l7 + ((lane >> 3) & 1) * 8;
    const int aco = (lane >> 4) * 8;
    const int bro = l7 + (lane >> 4) * 8;
    const int bco = ((lane >> 3) & 1) * 8;

    float acc[2][4][4] = {};

    auto compute = [&](int buf) {
        const uint32_t bA = sptr(sA + buf * AT);
        const uint32_t bB = sptr(sB + buf * BT);
        #pragma unroll
        for (int kk = 0; kk < 2; kk++) {
            uint32_t ah[2][4], bh[2][4];
            #pragma unroll
            for (int mt = 0; mt < 2; mt++) {
                const uint32_t off = ((wm * 32 + mt * 16 + aro) * SAS + kk * 16 + aco) * 2;
                ldm4(bA + off, ah[mt][0], ah[mt][1], ah[mt][2], ah[mt][3]);
            }
            #pragma unroll
            for (int pn = 0; pn < 2; pn++) {
                const uint32_t off = ((wn * 32 + pn * 16 + bro) * SAS + kk * 16 + bco) * 2;
                ldm4(bB + off, bh[pn][0], bh[pn][1], bh[pn][2], bh[pn][3]);
            }
            #pragma unroll
            for (int mt = 0; mt < 2; mt++)
                #pragma unroll
                for (int nt = 0; nt < 4; nt++)
                    mma_f16(acc[mt][nt], ah[mt],
                            bh[nt >> 1][(nt & 1) * 2], bh[nt >> 1][(nt & 1) * 2 + 1]);
        }
    };

    issue(0);
    issue(1);
    issue(2);
    for (int kt = 0; kt < NT; kt++) {
        CP_WAIT2();
        __syncthreads();
        issue(kt + 3);
        compute(kt & 3);
    }

    // ---- epilogues ----
    const int g = lane >> 2, tt = lane & 3;

    if (MODE == 1) {   // F1: tanh(v + cbias + t*w1t) -> h1 plane
        #pragma unroll
        for (int mt = 0; mt < 2; mt++)
            #pragma unroll
            for (int nt = 0; nt < 4; nt++) {
                const int c = n0 + wn * 32 + nt * 8 + tt * 2;
                const float2 wt = *(const float2*)&p.w1t[c];
                #pragma unroll
                for (int hr = 0; hr < 2; hr++) {
                    const int r = m0 + wm * 32 + mt * 16 + g + hr * 8;
                    const size_t off = (size_t)r * 512 + c;
                    const float2 cb = *(const float2*)&p.cbias[off];
                    const float v0 = ftanh(acc[mt][nt][hr * 2 + 0] + cb.x + p.t * wt.x);
                    const float v1 = ftanh(acc[mt][nt][hr * 2 + 1] + cb.y + p.t * wt.y);
                    ((unsigned*)p.Oh)[off >> 1] = pack_h1(v0, v1);
                }
            }
        return;
    }

    if (MODE == 2) {   // F2: tanh -> h2 + mA
        #pragma unroll
        for (int mt = 0; mt < 2; mt++)
            #pragma unroll
            for (int nt = 0; nt < 4; nt++) {
                const int c = n0 + wn * 32 + nt * 8 + tt * 2;
                const float2 bi = *(const float2*)&p.bias[c];
                #pragma unroll
                for (int hr = 0; hr < 2; hr++) {
                    const int r = m0 + wm * 32 + mt * 16 + g + hr * 8;
                    const size_t off = (size_t)r * 512 + c;
                    const float v0 = ftanh(acc[mt][nt][hr * 2 + 0] + bi.x);
                    const float v1 = ftanh(acc[mt][nt][hr * 2 + 1] + bi.y);
                    ((unsigned*)p.Oh)[off >> 1] = pack_h1(v0, v1);
                    const float2 gv = *(const float2*)&p.G3[off];
                    ((unsigned*)p.mA)[off >> 1] =
                        pack_h1(gv.x * (1.f - v0 * v0), gv.y * (1.f - v1 * v1));
                }
            }
        return;
    }

    if (MODE == 3) {   // B2 logdet dot
        float s[4] = {0.f, 0.f, 0.f, 0.f};
        #pragma unroll
        for (int mt = 0; mt < 2; mt++)
            #pragma unroll
            for (int nt = 0; nt < 4; nt++) {
                const int c = n0 + wn * 32 + nt * 8 + tt * 2;
                #pragma unroll
                for (int hr = 0; hr < 2; hr++) {
                    const int r = m0 + wm * 32 + mt * 16 + g + hr * 8;
                    const size_t off = (size_t)r * 512 + c;
                    const unsigned hh = *(const unsigned*)&p.h1[off];
                    const float2 e = *(const float2*)&p.E1[off];
                    const float h0 = up16(hh, 0), h1v = up16(hh, 1);
                    s[mt * 2 + hr] += acc[mt][nt][hr * 2 + 0] * (1.f - h0 * h0) * e.x
                                    + acc[mt][nt][hr * 2 + 1] * (1.f - h1v * h1v) * e.y;
                }
            }
        #pragma unroll
        for (int i = 0; i < 4; i++) {
            s[i] += __shfl_xor_sync(0xffffffffu, s[i], 1);
            s[i] += __shfl_xor_sync(0xffffffffu, s[i], 2);
        }
        __syncthreads();
        if (tt == 0) {
            #pragma unroll
            for (int mt = 0; mt < 2; mt++)
                #pragma unroll
                for (int hr = 0; hr < 2; hr++)
                    red[(wm * 32 + mt * 16 + g + hr * 8) * 2 + wn] = s[mt * 2 + hr];
        }
        __syncthreads();
        if (tid < 128)
            p.psum[(size_t)by * Bb + m0 + tid] = red[tid * 2] + red[tid * 2 + 1];
        return;
    }

    // MODE 4: F3 + RK4 (yin single plane)
    {
        #pragma unroll
        for (int mt = 0; mt < 2; mt++)
            #pragma unroll
            for (int nt = 0; nt < 4; nt++) {
                const int c = wn * 32 + nt * 8 + tt * 2;
                const float2 b3v = *(const float2*)&p.b3[c];
                #pragma unroll
                for (int hr = 0; hr < 2; hr++) {
                    const int r = m0 + wm * 32 + mt * 16 + g + hr * 8;
                    const size_t idx = (size_t)r * 64 + c;
                    const float kv0 = acc[mt][nt][hr * 2 + 0] + b3v.x;
                    const float kv1 = acc[mt][nt][hr * 2 + 1] + b3v.y;
                    const float2 base = (p.stage == 1) ? *(const float2*)&p.y[idx]
                                                       : *(const float2*)&p.yacc[idx];
                    const float ya0 = base.x + p.cacc * kv0;
                    const float ya1 = base.y + p.cacc * kv1;
                    float yi0, yi1;
                    if (p.stage == 4) {
                        *(float2*)&p.y[idx] = make_float2(ya0, ya1);
                        yi0 = ya0; yi1 = ya1;
                    } else {
                        *(float2*)&p.yacc[idx] = make_float2(ya0, ya1);
                        const float2 yv = *(const float2*)&p.y[idx];
                        yi0 = yv.x + p.cin * kv0;
                        yi1 = yv.y + p.cin * kv1;
                    }
                    ((unsigned*)p.Oh)[idx >> 1] = pack_h1(yi0, yi1);
                }
            }
    }
}

// ---------------- aux kernels ----------------
__device__ __forceinline__ void hsplit(float v, __half* h, __half* l, size_t i) {
    const __half hv = __float2half_rn(v);
    h[i] = hv;
    l[i] = __float2half_rn(v - __half2float(hv));
}
__global__ void prep_k(const float* __restrict__ eps, const float* __restrict__ W2,
                       const float* __restrict__ W3, const float* __restrict__ W1,
                       __half* eph, __half* epl,
                       __half* w2f, __half* w3f,
                       __half* w2tf, __half* w1ytf, __half* w3tf) {
    int i = blockIdx.x * 256 + threadIdx.x;
    if (i < Bb * Dd) { hsplit(eps[i], eph, epl, i); return; }
    i -= Bb * Dd;
    if (i < Hh * Hh) { w2f[i] = __float2half_rn(W2[i]); return; }
    i -= Hh * Hh;
    if (i < Hh * Dd) { w3f[i] = __float2half_rn(W3[i]); return; }
    i -= Hh * Dd;
    if (i < Hh * Hh) {
        const int r = i / Hh, c = i % Hh;
        w2tf[(size_t)c * Hh + r] = __float2half_rn(W2[i]);
        return;
    }
    i -= Hh * Hh;
    if (i < Dd * Hh) {
        const int r = i / Hh, c = i % Hh;
        w1ytf[(size_t)c * Dd + r] = __float2half_rn(W1[i]);
        return;
    }
    i -= Dd * Hh;
    if (i < Hh * Dd) {
        const int r = i / Dd, c = i % Dd;
        w3tf[(size_t)c * Hh + r] = __float2half_rn(W3[i]);
    }
}
__global__ void cbias_k(const float* __restrict__ cond, const float* __restrict__ W1c,
                        const float* __restrict__ b1, float* __restrict__ cb) {
    const int m = blockIdx.x;
    const int n = threadIdx.x * 4;
    float4 acc = *(const float4*)(b1 + n);
    #pragma unroll
    for (int k = 0; k < Cc; k++) {
        const float c = cond[m * Cc + k];
        const float4 w = *(const float4*)(W1c + (size_t)k * Hh + n);
        acc.x = fmaf(c, w.x, acc.x); acc.y = fmaf(c, w.y, acc.y);
        acc.z = fmaf(c, w.z, acc.z); acc.w = fmaf(c, w.w, acc.w);
    }
    *(float4*)(cb + (size_t)m * Hh + n) = acc;
}
__global__ void init_k(const float* __restrict__ x, float* __restrict__ y,
                       __half* __restrict__ yinh, float* __restrict__ ld) {
    const int i = blockIdx.x * blockDim.x + threadIdx.x;
    if (i < Bb * Dd) {
        const float v = x[i];
        y[i] = v;
        yinh[i] = __float2half_rn(v);
    }
    if (i < Bb) ld[i] = 0.f;
}
__global__ void out_k(const float* __restrict__ y, const float* __restrict__ ld,
                      const float* __restrict__ psum, float coef, float* __restrict__ out) {
    const int i = blockIdx.x * blockDim.x + threadIdx.x;
    if (i >= Bb * (Dd + 1)) return;
    const int m = i / (Dd + 1), c = i % (Dd + 1);
    if (c < Dd) {
        out[i] = y[(size_t)m * Dd + c];
    } else {
        float s = 0.f;
        #pragma unroll
        for (int c2 = 0; c2 < 8; c2++) s += psum[c2 * Bb + m];
        out[i] = ld[m] + coef * s;
    }
}

// ---------------- host ----------------
extern "C" void kernel_launch(void* const* d_in, const int* in_sizes, int n_in,
                              void* d_out, int out_size) {
    const float* x    = (const float*)d_in[0];
    const float* cond = (const float*)d_in[1];
    const float* eps  = (const float*)d_in[2];
    const float* W1   = (const float*)d_in[3];
    const float* b1   = (const float*)d_in[4];
    const float* W2   = (const float*)d_in[5];
    const float* b2   = (const float*)d_in[6];
    const float* W3   = (const float*)d_in[7];
    const float* b3   = (const float*)d_in[8];
    float* out = (float*)d_out;

    static cudaStream_t s2 = nullptr;
    static cudaEvent_t evF2 = nullptr, evB2a = nullptr, evB2b = nullptr;
    if (s2 == nullptr) {
        cudaStreamCreateWithFlags(&s2, cudaStreamNonBlocking);
        cudaEventCreateWithFlags(&evF2, cudaEventDisableTiming);
        cudaEventCreateWithFlags(&evB2a, cudaEventDisableTiming);
        cudaEventCreateWithFlags(&evB2b, cudaEventDisableTiming);
        cudaFuncSetAttribute(pro_k, cudaFuncAttributeMaxDynamicSharedMemorySize, SMEM_SM);
        cudaFuncSetAttribute(big_k<1>, cudaFuncAttributeMaxDynamicSharedMemorySize, SMEM_BIG);
        cudaFuncSetAttribute(big_k<2>, cudaFuncAttributeMaxDynamicSharedMemorySize, SMEM_BIG);
        cudaFuncSetAttribute(big_k<3>, cudaFuncAttributeMaxDynamicSharedMemorySize, SMEM_BIG);
        cudaFuncSetAttribute(big_k<4>, cudaFuncAttributeMaxDynamicSharedMemorySize, SMEM_BIG);
    }

    #define SYM(T, v, s) T* v; { void* _p; cudaGetSymbolAddress(&_p, s); v = (T*)_p; }
    SYM(float, y, g_y) SYM(float, yacc, g_yacc) SYM(float, cb, g_cb)
    SYM(float, G3, g_G3) SYM(float, E1, g_E1) SYM(float, ld, g_ld) SYM(float, psum, g_psum)
    SYM(__half, h1h, g_h1h) SYM(__half, h2h, g_h2h) SYM(__half, mAh, g_mAh)
    SYM(__half, yinh, g_yinh)
    SYM(__half, epsh, g_epsh) SYM(__half, epsl, g_epsl)
    SYM(__half, W2f, g_W2f) SYM(__half, W2Tf, g_W2Tf)
    SYM(__half, W3f, g_W3f) SYM(__half, W3Tf, g_W3Tf)
    SYM(__half, W1yTf, g_W1yTf)
    #undef SYM

    init_k<<<(Bb * Dd + 255) / 256, 256>>>(x, y, yinh, ld);

    constexpr int PREP_N = Bb * Dd + 2 * Hh * Hh + 3 * Hh * Dd;
    const float dt = 1.0f / NS;
    float prev_cl = 0.f;
    int gs = 0;

    for (int ib = 0; ib < NB; ib++) {
        const float* W1b  = W1 + (size_t)ib * (Dd + Cc + 1) * Hh;
        const float* b1b  = b1 + (size_t)ib * Hh;
        const float* W2b  = W2 + (size_t)ib * Hh * Hh;
        const float* b2b  = b2 + (size_t)ib * Hh;
        const float* W3b  = W3 + (size_t)ib * Hh * Dd;
        const float* b3b  = b3 + (size_t)ib * Dd;
        const float* epsb = eps + (size_t)ib * Bb * Dd;
        float* cbb = cb + (size_t)ib * Bb * Hh;
        float* G3b = G3 + (size_t)ib * Bb * Hh;
        float* E1b = E1 + (size_t)ib * Bb * Hh;
        __half *eph = epsh + (size_t)ib * Bb * Dd, *epl = epsl + (size_t)ib * Bb * Dd;
        __half* w2f  = W2f  + (size_t)ib * Hh * Hh;
        __half* w2tf = W2Tf + (size_t)ib * Hh * Hh;
        __half* w3f  = W3f  + (size_t)ib * Hh * Dd;
        __half* w3tf = W3Tf + (size_t)ib * Dd * Hh;
        __half* w1ytf = W1yTf + (size_t)ib * Hh * Dd;

        prep_k<<<(PREP_N + 255) / 256, 256>>>(epsb, W2b, W3b, W1b,
            eph, epl, w2f, w3f, w2tf, w1ytf, w3tf);
        cbias_k<<<Bb, 128>>>(cond, W1b + (size_t)Dd * Hh, b1b, cbb);

        {   // merged G3 (by<8) + E1 (by>=8)
            P p{}; p.A = eph; p.Al = epl;
            p.B = w3f; p.C = G3b;
            p.B2f = w1ytf; p.C2 = E1b;
            pro_k<<<dim3(32, 16), 256, SMEM_SM>>>(p);
        }

        for (int is = 0; is < NS; is++) {
            const float tbase = is * dt;
            for (int st = 1; st <= 4; st++) {
                const float t = tbase + (st == 1 ? 0.f : (st == 4 ? dt : 0.5f * dt));
                const float cacc = (st == 1 || st == 4) ? dt / 6.f : dt / 3.f;
                const float cin  = (st == 3) ? dt : 0.5f * dt;
                const int q = gs & 1;
                __half* h1q = h1h + (size_t)q * Bb * Hh;
                __half* mAq = mAh + (size_t)q * Bb * Hh;
                float* psq  = psum + (size_t)q * 8 * Bb;
                float* pspv = psum + (size_t)(q ^ 1) * 8 * Bb;
                cudaEvent_t evq = q ? evB2b : evB2a;

                if (gs >= 2) cudaStreamWaitEvent(0, evq, 0);   // h1[q]/mA[q] free

                {   // F1 -> h1[q]
                    P p{}; p.A = yinh; p.B = w1ytf;
                    p.cbias = cbb; p.w1t = W1b + (size_t)(Dd + Cc) * Hh; p.t = t;
                    p.Oh = h1q;
                    big_k<1><<<dim3(32, 8), 256, SMEM_BIG>>>(p);
                }
                {   // F2 -> h2 + mA[q]
                    P p{}; p.A = h1q; p.B = w2tf;
                    p.bias = b2b; p.Oh = h2h; p.G3 = G3b; p.mA = mAq;
                    big_k<2><<<dim3(32, 8), 256, SMEM_BIG>>>(p);
                }
                cudaEventRecord(evF2, 0);
                {   // F3 + RK4 (main)
                    P p{}; p.A = h2h; p.B = w3tf;
                    p.b3 = b3b; p.y = y; p.yacc = yacc; p.Oh = yinh;
                    p.stage = st; p.cacc = cacc; p.cin = cin;
                    big_k<4><<<dim3(32, 1), 256, SMEM_BIG>>>(p);
                }
                cudaStreamWaitEvent(s2, evF2, 0);
                {   // B2 + logdet -> psum[q]; fold rider for psum[q^1] (stream 2)
                    P p{}; p.A = mAq; p.B = w2f;
                    p.h1 = h1q; p.E1 = E1b;
                    p.psum = psq; p.psumPrev = pspv;
                    p.ld = ld; p.foldcoef = prev_cl;
                    big_k<3><<<dim3(32, 9), 256, SMEM_BIG, s2>>>(p);
                }
                cudaEventRecord(evq, s2);

                prev_cl = cacc;
                gs++;
            }
        }
    }

    cudaStreamWaitEvent(0, evB2a, 0);
    cudaStreamWaitEvent(0, evB2b, 0);
    out_k<<<(Bb * (Dd + 1) + 255) / 256, 256>>>(
        y, ld, psum + (size_t)((gs - 1) & 1) * 8 * Bb, prev_cl, out);
}